// round 16
// baseline (speedup 1.0000x reference)
#include <cuda_runtime.h>
#include <cuda_bf16.h>
#include <mma.h>
#include <cstdint>

using namespace nvcuda;

#define BSZ 2
#define LEN 2048
#define NHD 24
#define DH  64
#define DS  128

#define NPAIR (BSZ*NHD)     // 48
#define TC    64
#define NCH   (LEN/TC)      // 32
#define THREADS 256

#define LDC 136   // bf16 row pitch, 128-wide rows (pass1)
#define LDX 72    // bf16 row pitch, 64-wide rows
#define LDK 72    // bf16 row pitch, 64-wide k-half rows (pass3)
#define LDH 72
#define LDW 68    // fp32 row pitch for W/Y

// ------------- device scratch (no allocation allowed) -------------
__device__ float         g_S  [NPAIR*NCH*DH*DS];   // [s][d] per chunk
__device__ __nv_bfloat16 g_Hhi[NPAIR*NCH*DH*DS];   // [s][d], bf16 hi
__device__ __nv_bfloat16 g_Hlo[NPAIR*NCH*DH*DS];   // [s][d], bf16 lo
__device__ float         g_P  [NPAIR*NCH];

__device__ __forceinline__ float neg_sp_abs(float a, float d) {
    float v  = a + d;
    float sp = (v > 20.f) ? v : log1pf(expf(v));
    return -sp * fabsf(a);                          // log(a_bar) <= 0
}

// 2-barrier inclusive scan of buf[0..63]
__device__ __forceinline__ void scan64(float* buf, int tid) {
    if (tid < 64) {
        float v = buf[tid];
        #pragma unroll
        for (int o = 1; o < 32; o <<= 1) {
            float u = __shfl_up_sync(0xffffffffu, v, o);
            if ((tid & 31) >= o) v += u;
        }
        buf[tid] = v;
    }
    __syncthreads();
    if (tid >= 32 && tid < 64) buf[tid] += buf[31];
    __syncthreads();
}

__device__ __forceinline__ void split4(float4 v, uint2& hi, uint2& lo) {
    __nv_bfloat16 h0 = __float2bfloat16(v.x), h1 = __float2bfloat16(v.y);
    __nv_bfloat16 h2 = __float2bfloat16(v.z), h3 = __float2bfloat16(v.w);
    __nv_bfloat16 l0 = __float2bfloat16(v.x - __bfloat162float(h0));
    __nv_bfloat16 l1 = __float2bfloat16(v.y - __bfloat162float(h1));
    __nv_bfloat16 l2 = __float2bfloat16(v.z - __bfloat162float(h2));
    __nv_bfloat16 l3 = __float2bfloat16(v.w - __bfloat162float(h3));
    hi.x = (uint32_t)__bfloat16_as_ushort(h0) | ((uint32_t)__bfloat16_as_ushort(h1) << 16);
    hi.y = (uint32_t)__bfloat16_as_ushort(h2) | ((uint32_t)__bfloat16_as_ushort(h3) << 16);
    lo.x = (uint32_t)__bfloat16_as_ushort(l0) | ((uint32_t)__bfloat16_as_ushort(l1) << 16);
    lo.y = (uint32_t)__bfloat16_as_ushort(l2) | ((uint32_t)__bfloat16_as_ushort(l3) << 16);
}

__device__ __forceinline__ unsigned smem_u32(const void* p) {
    return (unsigned)__cvta_generic_to_shared(p);
}
__device__ __forceinline__ void cpa16(unsigned dst, const void* src) {
    asm volatile("cp.async.cg.shared.global [%0], [%1], 16;\n" :: "r"(dst), "l"(src));
}

// =================================================================
// Pass 1 (WMMA, transpose-free): S'[s,d] = sum_t B[t,s] (w_t x[t,d])
// 3 CTAs/SM. x staged via cp.async (raw fp32) overlapped with the
// decay scan + B staging; split/scale from smem afterwards.
// =================================================================
#define P1_LCP  0
#define P1_LW   256
#define P1_BHI  512
#define P1_BLO  (P1_BHI + TC*LDC*2)
#define P1_XHI  (P1_BLO + TC*LDC*2)
#define P1_XLO  (P1_XHI + TC*LDX*2)
#define P1_XRAW (P1_XLO + TC*LDX*2)    // fp32 64x64 raw x
#define SMEM1   (P1_XRAW + TC*DH*4)    // 70144 -> 3 CTAs/SM (210 KB)

__global__ __launch_bounds__(THREADS, 3)
void pass1_kernel(const float* __restrict__ x,
                  const float* __restrict__ Bm,
                  const float* __restrict__ A,
                  const float* __restrict__ dp) {
    extern __shared__ __align__(128) char smem[];
    float* lcp  = (float*)(smem + P1_LCP);
    float* lw   = (float*)(smem + P1_LW);
    float* xraw = (float*)(smem + P1_XRAW);
    const __nv_bfloat16* Bhi = (const __nv_bfloat16*)(smem + P1_BHI);
    const __nv_bfloat16* Blo = (const __nv_bfloat16*)(smem + P1_BLO);
    const __nv_bfloat16* Xhi = (const __nv_bfloat16*)(smem + P1_XHI);
    const __nv_bfloat16* Xlo = (const __nv_bfloat16*)(smem + P1_XLO);

    const int tid  = threadIdx.x;
    const int ch   = blockIdx.x;
    const int pair = blockIdx.y;
    const int b    = pair / NHD;
    const int hh   = pair % NHD;
    const size_t rowbase = ((size_t)b * LEN + ch * TC) * NHD + hh;

    // ---- x raw staging via cp.async (fires first, no dependencies) ----
    {
        unsigned xb = smem_u32(xraw);
        #pragma unroll
        for (int j = 0; j < 4; ++j) {
            int i = tid + j * THREADS;          // float4 idx; t = i>>4, c = i&15
            int t = i >> 4, c = i & 15;
            cpa16(xb + i * 16, x + (rowbase + (size_t)t*NHD) * DH + c * 4);
        }
        asm volatile("cp.async.commit_group;\n" ::: "memory");
    }

    // ---- decay logs (A loads overlap with x cp.async) ----
    if (tid < TC) lcp[tid] = neg_sp_abs(A[rowbase + (size_t)tid * NHD], dp[hh]);

    // ---- stage B [t][s] bf16 hi/lo (independent of the scan) ----
    for (int i = tid; i < TC * 32; i += THREADS) {
        int t = i >> 5, c4 = i & 31;
        float4 v = ((const float4*)(Bm + (rowbase + (size_t)t*NHD) * DS))[c4];
        uint2 hi, lo;  split4(v, hi, lo);
        int off = t * (LDC*2) + c4 * 8;
        *(uint2*)(smem + P1_BHI + off) = hi;
        *(uint2*)(smem + P1_BLO + off) = lo;
    }
    __syncthreads();
    scan64(lcp, tid);
    if (tid < TC) lw[tid] = __expf(lcp[TC-1] - lcp[tid]);
    if (tid == 0) g_P[pair*NCH + ch] = __expf(lcp[TC-1]);
    asm volatile("cp.async.wait_group 0;\n" ::: "memory");
    __syncthreads();

    // ---- split + scale x from smem raw ----
    #pragma unroll
    for (int j = 0; j < 4; ++j) {
        int i = tid + j * THREADS;
        int t = i >> 4, c = i & 15;
        float4 v = ((const float4*)xraw)[i];
        float wt = lw[t];
        v.x *= wt; v.y *= wt; v.z *= wt; v.w *= wt;
        uint2 hi, lo;  split4(v, hi, lo);
        int off = t * (LDX*2) + c * 8;
        *(uint2*)(smem + P1_XHI + off) = hi;
        *(uint2*)(smem + P1_XLO + off) = lo;
    }
    __syncthreads();

    // WMMA: warp w owns m-tile (s) = w, n-tiles (d) 0..3
    const int w = tid >> 5;
    wmma::fragment<wmma::accumulator, 16, 16, 16, float> acc[4];
    #pragma unroll
    for (int nt = 0; nt < 4; ++nt) wmma::fill_fragment(acc[nt], 0.f);
    wmma::fragment<wmma::matrix_a, 16, 16, 16, __nv_bfloat16, wmma::col_major> ahi, alo;
    wmma::fragment<wmma::matrix_b, 16, 16, 16, __nv_bfloat16, wmma::row_major> bhi, blo;

    #pragma unroll
    for (int ks = 0; ks < 4; ++ks) {
        wmma::load_matrix_sync(ahi, Bhi + ks*16*LDC + w*16, LDC);
        wmma::load_matrix_sync(alo, Blo + ks*16*LDC + w*16, LDC);
        #pragma unroll
        for (int nt = 0; nt < 4; ++nt) {
            wmma::load_matrix_sync(bhi, Xhi + ks*16*LDX + nt*16, LDX);
            wmma::load_matrix_sync(blo, Xlo + ks*16*LDX + nt*16, LDX);
            wmma::mma_sync(acc[nt], ahi, bhi, acc[nt]);
            wmma::mma_sync(acc[nt], ahi, blo, acc[nt]);
            wmma::mma_sync(acc[nt], alo, bhi, acc[nt]);
        }
    }
    float* Sdst = g_S + ((size_t)(pair*NCH + ch)) * DH * DS;   // [s][d]
    #pragma unroll
    for (int nt = 0; nt < 4; ++nt)
        wmma::store_matrix_sync(Sdst + w*16*DH + nt*16, acc[nt],
                                DH, wmma::mem_row_major);
}

// =================================================================
// Pass 2: exclusive chunk scan; 2 independent chains per thread
// (static indexing only), prefetch depth 2 each.
// =================================================================
__global__ __launch_bounds__(THREADS, 8)
void pass2_kernel() {
    const int pair = blockIdx.x;
    const int idx  = blockIdx.y * THREADS + threadIdx.x;   // [0,1024)
    const float* Pp = g_P + pair * NCH;
    const size_t baseA = (size_t)pair * NCH * 2048 + idx;
    const size_t baseB = baseA + 1024;

    float4 HrA = make_float4(0.f, 0.f, 0.f, 0.f);
    float4 HrB = make_float4(0.f, 0.f, 0.f, 0.f);
    float4 nA0 = ((const float4*)g_S)[baseA];
    float4 nB0 = ((const float4*)g_S)[baseB];
    float4 nA1 = ((const float4*)g_S)[baseA + 2048];
    float4 nB1 = ((const float4*)g_S)[baseB + 2048];

    #pragma unroll 4
    for (int ch = 0; ch < NCH; ++ch) {
        float4 curA = nA0;  nA0 = nA1;
        float4 curB = nB0;  nB0 = nB1;
        if (ch + 2 < NCH) {
            nA1 = ((const float4*)g_S)[baseA + (size_t)(ch+2)*2048];
            nB1 = ((const float4*)g_S)[baseB + (size_t)(ch+2)*2048];
        }
        uint2 hi, lo;
        split4(HrA, hi, lo);
        ((uint2*)g_Hhi)[baseA + (size_t)ch*2048] = hi;
        ((uint2*)g_Hlo)[baseA + (size_t)ch*2048] = lo;
        split4(HrB, hi, lo);
        ((uint2*)g_Hhi)[baseB + (size_t)ch*2048] = hi;
        ((uint2*)g_Hlo)[baseB + (size_t)ch*2048] = lo;
        const float P = Pp[ch];
        HrA.x = P*HrA.x + curA.x;  HrA.y = P*HrA.y + curA.y;
        HrA.z = P*HrA.z + curA.z;  HrA.w = P*HrA.w + curA.w;
        HrB.x = P*HrB.x + curB.x;  HrB.y = P*HrB.y + curB.y;
        HrB.z = P*HrB.z + curB.z;  HrB.w = P*HrB.w + curB.w;
    }
}

// =================================================================
// Pass 3 (WMMA, k-split staging -> 3 CTAs/SM): unchanged from R15.
// =================================================================
#define P3_LCP  0
#define P3_GINV 256
#define P3_ELC  512
#define P3_STG  1024
#define P3_CHI  (P3_STG)
#define P3_CLO  (P3_CHI + TC*LDK*2)
#define P3_BHI  (P3_CLO + TC*LDK*2)
#define P3_BLO  (P3_BHI + TC*LDK*2)
#define P3_HHI  (P3_BLO + TC*LDK*2)
#define P3_HLO  (P3_HHI + TC*LDH*2)
#define P3_STGE (P3_HLO + TC*LDH*2)        // 56320
#define P3_X    (P3_STGE)                  // fp32 64x64 (dedicated)
#define SMEM3   (P3_X + TC*DH*4)           // 72704 -> 3 CTAs/SM
#define P3_W    (P3_STG)                   // fp32 64 x LDW (alias)
#define P3_Y    (P3_W + TC*LDW*4)

__global__ __launch_bounds__(THREADS, 3)
void pass3_kernel(const float* __restrict__ x,
                  const float* __restrict__ Bm,
                  const float* __restrict__ Cm,
                  const float* __restrict__ A,
                  const float* __restrict__ dp,
                  float* __restrict__ out) {
    extern __shared__ __align__(128) char smem[];
    float* lcp  = (float*)(smem + P3_LCP);
    float* ginv = (float*)(smem + P3_GINV);
    float* elc  = (float*)(smem + P3_ELC);
    float* Wsh  = (float*)(smem + P3_W);
    float* Ysh  = (float*)(smem + P3_Y);
    float* xs   = (float*)(smem + P3_X);

    const int tid  = threadIdx.x;
    const int ch   = blockIdx.x;
    const int pair = blockIdx.y;
    const int b    = pair / NHD;
    const int hh   = pair % NHD;
    const size_t rowbase = ((size_t)b * LEN + ch * TC) * NHD + hh;

    // ---- stage x via cp.async into dedicated buffer ----
    {
        unsigned xb = smem_u32(xs);
        #pragma unroll
        for (int j = 0; j < 4; ++j) {
            int i = tid + j * THREADS;
            int t = i >> 4, c = i & 15;
            cpa16(xb + i * 16, x + (rowbase + (size_t)t*NHD) * DH + c * 4);
        }
        asm volatile("cp.async.commit_group;\n" ::: "memory");
    }

    if (tid < TC) {
        float la = neg_sp_abs(A[rowbase + (size_t)tid * NHD], dp[hh]);
        lcp[tid]  = la;
        ginv[tid] = fminf(__expf(-la), 1e30f);
    }
    __syncthreads();
    scan64(lcp, tid);
    if (tid < TC) elc[tid] = __expf(lcp[tid]);

    // ---- GEMM1 over two k-halves ----
    const int w = tid >> 5;
    wmma::fragment<wmma::accumulator, 16, 16, 16, float> acc[4];
    #pragma unroll
    for (int nt = 0; nt < 4; ++nt) wmma::fill_fragment(acc[nt], 0.f);

    const __nv_bfloat16* Hh_g = g_Hhi + (size_t)(pair*NCH + ch) * (DH*DS);
    const __nv_bfloat16* Hl_g = g_Hlo + (size_t)(pair*NCH + ch) * (DH*DS);

    #pragma unroll
    for (int kh = 0; kh < 2; ++kh) {
        {
            unsigned hb = smem_u32(smem + P3_HHI);
            unsigned lb = smem_u32(smem + P3_HLO);
            const uint4* Hh16 = (const uint4*)(Hh_g + kh * 64 * DH);
            const uint4* Hl16 = (const uint4*)(Hl_g + kh * 64 * DH);
            #pragma unroll
            for (int j = 0; j < 2; ++j) {
                int i = tid + j * THREADS;      // [0,512): s = i>>3, c = i&7
                int s = i >> 3, c = i & 7;
                unsigned off = s * (LDH*2) + c * 16;
                cpa16(hb + off, Hh16 + i);
                cpa16(lb + off, Hl16 + i);
            }
            asm volatile("cp.async.commit_group;\n" ::: "memory");
        }
        for (int i = tid; i < TC * 16; i += THREADS) {
            int t = i >> 4, c4 = i & 15;
            const size_t gofs = (rowbase + (size_t)t*NHD) * DS + kh * 64;
            float4 vc = ((const float4*)(Cm + gofs))[c4];
            float4 vb = ((const float4*)(Bm + gofs))[c4];
            uint2 hi, lo;
            int off = t * (LDK*2) + c4 * 8;
            split4(vc, hi, lo);
            *(uint2*)(smem + P3_CHI + off) = hi;
            *(uint2*)(smem + P3_CLO + off) = lo;
            split4(vb, hi, lo);
            *(uint2*)(smem + P3_BHI + off) = hi;
            *(uint2*)(smem + P3_BLO + off) = lo;
        }
        asm volatile("cp.async.wait_group 0;\n" ::: "memory");
        __syncthreads();

        {
            wmma::fragment<wmma::matrix_a, 16, 16, 16, __nv_bfloat16, wmma::row_major> ahi, alo;
            const __nv_bfloat16* Cb = (const __nv_bfloat16*)(smem + P3_CHI);
            const __nv_bfloat16* Cl = (const __nv_bfloat16*)(smem + P3_CLO);
            if (w < 4) {   // W = C . B^T  (causal skip)
                const __nv_bfloat16* Db = (const __nv_bfloat16*)(smem + P3_BHI);
                const __nv_bfloat16* Dl = (const __nv_bfloat16*)(smem + P3_BLO);
                wmma::fragment<wmma::matrix_b, 16, 16, 16, __nv_bfloat16, wmma::col_major> bhi, blo;
                #pragma unroll
                for (int ks = 0; ks < 4; ++ks) {
                    wmma::load_matrix_sync(ahi, Cb + w*16*LDK + ks*16, LDK);
                    wmma::load_matrix_sync(alo, Cl + w*16*LDK + ks*16, LDK);
                    #pragma unroll
                    for (int nt = 0; nt < 4; ++nt) {
                        if (nt > w) break;
                        wmma::load_matrix_sync(bhi, Db + nt*16*LDK + ks*16, LDK);
                        wmma::load_matrix_sync(blo, Dl + nt*16*LDK + ks*16, LDK);
                        wmma::mma_sync(acc[nt], ahi, bhi, acc[nt]);
                        wmma::mma_sync(acc[nt], ahi, blo, acc[nt]);
                        wmma::mma_sync(acc[nt], alo, bhi, acc[nt]);
                    }
                }
            } else {       // Y1 = C . H'
                const int mt = w - 4;
                const __nv_bfloat16* Hb = (const __nv_bfloat16*)(smem + P3_HHI);
                const __nv_bfloat16* Hl = (const __nv_bfloat16*)(smem + P3_HLO);
                wmma::fragment<wmma::matrix_b, 16, 16, 16, __nv_bfloat16, wmma::row_major> bhi, blo;
                #pragma unroll
                for (int ks = 0; ks < 4; ++ks) {
                    wmma::load_matrix_sync(ahi, Cb + mt*16*LDK + ks*16, LDK);
                    wmma::load_matrix_sync(alo, Cl + mt*16*LDK + ks*16, LDK);
                    #pragma unroll
                    for (int nt = 0; nt < 4; ++nt) {
                        wmma::load_matrix_sync(bhi, Hb + ks*16*LDH + nt*16, LDH);
                        wmma::load_matrix_sync(blo, Hl + ks*16*LDH + nt*16, LDH);
                        wmma::mma_sync(acc[nt], ahi, bhi, acc[nt]);
                        wmma::mma_sync(acc[nt], ahi, blo, acc[nt]);
                        wmma::mma_sync(acc[nt], alo, bhi, acc[nt]);
                    }
                }
            }
        }
        __syncthreads();
    }

    // ---- store W / Y into alias region ----
    if (w < 4) {
        #pragma unroll
        for (int nt = 0; nt < 4; ++nt) {
            if (nt > w) break;
            wmma::store_matrix_sync(Wsh + w*16*LDW + nt*16, acc[nt],
                                    LDW, wmma::mem_row_major);
        }
    } else {
        #pragma unroll
        for (int nt = 0; nt < 4; ++nt)
            wmma::store_matrix_sync(Ysh + (w-4)*16*LDW + nt*16, acc[nt],
                                    LDW, wmma::mem_row_major);
    }
    __syncthreads();

    // ---- epilogue: decay/mask W, scale Y1 ----
    {
        const int t  = tid >> 2;
        const int s0 = (tid & 3) * 16;
        float f = (s0 <= t) ? __expf(lcp[t] - lcp[s0]) : 0.f;
        float* wr = Wsh + t * LDW + s0;
        float* yr = Ysh + t * LDW + s0;
        const float et = elc[t];
        #pragma unroll
        for (int i2 = 0; i2 < 16; ++i2) {
            int s = s0 + i2;
            if (i2) f *= ginv[s];
            wr[i2] = (s <= t) ? f * wr[i2] : 0.f;
            yr[i2] = et * yr[i2];
        }
    }
    __syncthreads();

    // ---- GEMM2: Y = Y1 + W . x  (causal, fp32), warp-balanced ----
    {
        const int lane = tid & 31;
        const int wq   = tid >> 5;
        #pragma unroll
        for (int half = 0; half < 2; ++half) {
            const int r = half ? (15 - wq) : wq;
            float ya0[4], ya1[4];
            #pragma unroll
            for (int i = 0; i < 4; ++i) {
                float2 yv = *(const float2*)(Ysh + (4*r + i) * LDW + 2*lane);
                ya0[i] = yv.x;  ya1[i] = yv.y;
            }
            for (int s4 = 0; s4 <= r; ++s4) {
                float4 Wf[4];
                float2 xf[4];
                #pragma unroll
                for (int i = 0; i < 4; ++i)
                    Wf[i] = *(const float4*)(Wsh + (4*r + i) * LDW + 4*s4);
                #pragma unroll
                for (int k = 0; k < 4; ++k)
                    xf[k] = *(const float2*)(xs + (4*s4 + k) * DH + 2*lane);
                #pragma unroll
                for (int i = 0; i < 4; ++i) {
                    ya0[i] += Wf[i].x*xf[0].x + Wf[i].y*xf[1].x
                            + Wf[i].z*xf[2].x + Wf[i].w*xf[3].x;
                    ya1[i] += Wf[i].x*xf[0].y + Wf[i].y*xf[1].y
                            + Wf[i].z*xf[2].y + Wf[i].w*xf[3].y;
                }
            }
            #pragma unroll
            for (int i = 0; i < 4; ++i) {
                float* yout = out + (rowbase + (size_t)(4*r + i) * NHD) * DH + 2*lane;
                *(float2*)yout = make_float2(ya0[i], ya1[i]);
            }
        }
    }
}

// ------------- launch -------------
extern "C" void kernel_launch(void* const* d_in, const int* in_sizes, int n_in,
                              void* d_out, int out_size) {
    const float* x  = (const float*)d_in[0];
    const float* A  = (const float*)d_in[1];
    const float* Bm = (const float*)d_in[2];
    const float* Cm = (const float*)d_in[3];
    const float* dp = (const float*)d_in[4];
    (void)in_sizes; (void)n_in; (void)out_size;

    cudaFuncSetAttribute(pass1_kernel, cudaFuncAttributeMaxDynamicSharedMemorySize, SMEM1);
    cudaFuncSetAttribute(pass3_kernel, cudaFuncAttributeMaxDynamicSharedMemorySize, SMEM3);

    dim3 grid(NCH, NPAIR);
    pass1_kernel<<<grid, THREADS, SMEM1>>>(x, Bm, A, dp);
    pass2_kernel<<<dim3(NPAIR, 4), THREADS>>>();
    pass3_kernel<<<grid, THREADS, SMEM3>>>(x, Bm, Cm, A, dp, (float*)d_out);
}

// round 17
// speedup vs baseline: 1.1503x; 1.1503x over previous
#include <cuda_runtime.h>
#include <cuda_bf16.h>
#include <mma.h>
#include <cstdint>

using namespace nvcuda;

#define BSZ 2
#define LEN 2048
#define NHD 24
#define DH  64
#define DS  128

#define NPAIR (BSZ*NHD)     // 48
#define TC    64
#define NCH   (LEN/TC)      // 32
#define THREADS 256

#define LDC 136   // bf16 row pitch, 128-wide rows (pass1)
#define LDX 72    // bf16 row pitch, 64-wide rows
#define LDK 72    // bf16 row pitch, 64-wide k-half rows (pass3)
#define LDH 72
#define LDW 68    // fp32 row pitch for W/Y

// ------------- device scratch (no allocation allowed) -------------
__device__ float         g_S  [NPAIR*NCH*DH*DS];   // [s][d] per chunk
__device__ __nv_bfloat16 g_Hhi[NPAIR*NCH*DH*DS];   // [s][d], bf16 hi
__device__ __nv_bfloat16 g_Hlo[NPAIR*NCH*DH*DS];   // [s][d], bf16 lo
__device__ float         g_P  [NPAIR*NCH];

__device__ __forceinline__ float neg_sp_abs(float a, float d) {
    float v  = a + d;
    float sp = (v > 20.f) ? v : log1pf(expf(v));
    return -sp * fabsf(a);                          // log(a_bar) <= 0
}

// 2-barrier inclusive scan of buf[0..63]
__device__ __forceinline__ void scan64(float* buf, int tid) {
    if (tid < 64) {
        float v = buf[tid];
        #pragma unroll
        for (int o = 1; o < 32; o <<= 1) {
            float u = __shfl_up_sync(0xffffffffu, v, o);
            if ((tid & 31) >= o) v += u;
        }
        buf[tid] = v;
    }
    __syncthreads();
    if (tid >= 32 && tid < 64) buf[tid] += buf[31];
    __syncthreads();
}

__device__ __forceinline__ void split4(float4 v, uint2& hi, uint2& lo) {
    __nv_bfloat16 h0 = __float2bfloat16(v.x), h1 = __float2bfloat16(v.y);
    __nv_bfloat16 h2 = __float2bfloat16(v.z), h3 = __float2bfloat16(v.w);
    __nv_bfloat16 l0 = __float2bfloat16(v.x - __bfloat162float(h0));
    __nv_bfloat16 l1 = __float2bfloat16(v.y - __bfloat162float(h1));
    __nv_bfloat16 l2 = __float2bfloat16(v.z - __bfloat162float(h2));
    __nv_bfloat16 l3 = __float2bfloat16(v.w - __bfloat162float(h3));
    hi.x = (uint32_t)__bfloat16_as_ushort(h0) | ((uint32_t)__bfloat16_as_ushort(h1) << 16);
    hi.y = (uint32_t)__bfloat16_as_ushort(h2) | ((uint32_t)__bfloat16_as_ushort(h3) << 16);
    lo.x = (uint32_t)__bfloat16_as_ushort(l0) | ((uint32_t)__bfloat16_as_ushort(l1) << 16);
    lo.y = (uint32_t)__bfloat16_as_ushort(l2) | ((uint32_t)__bfloat16_as_ushort(l3) << 16);
}

__device__ __forceinline__ unsigned smem_u32(const void* p) {
    return (unsigned)__cvta_generic_to_shared(p);
}
__device__ __forceinline__ void cpa16(unsigned dst, const void* src) {
    asm volatile("cp.async.cg.shared.global [%0], [%1], 16;\n" :: "r"(dst), "l"(src));
}

// =================================================================
// Pass 1 (WMMA, transpose-free): S'[s,d] = sum_t B[t,s] (w_t x[t,d])
// 3 CTAs/SM. x staged via cp.async (raw fp32) overlapped with the
// decay scan + B staging; split/scale from smem afterwards. (R16, measured)
// =================================================================
#define P1_LCP  0
#define P1_LW   256
#define P1_BHI  512
#define P1_BLO  (P1_BHI + TC*LDC*2)
#define P1_XHI  (P1_BLO + TC*LDC*2)
#define P1_XLO  (P1_XHI + TC*LDX*2)
#define P1_XRAW (P1_XLO + TC*LDX*2)    // fp32 64x64 raw x
#define SMEM1   (P1_XRAW + TC*DH*4)    // 70144 -> 3 CTAs/SM (210 KB)

__global__ __launch_bounds__(THREADS, 3)
void pass1_kernel(const float* __restrict__ x,
                  const float* __restrict__ Bm,
                  const float* __restrict__ A,
                  const float* __restrict__ dp) {
    extern __shared__ __align__(128) char smem[];
    float* lcp  = (float*)(smem + P1_LCP);
    float* lw   = (float*)(smem + P1_LW);
    float* xraw = (float*)(smem + P1_XRAW);
    const __nv_bfloat16* Bhi = (const __nv_bfloat16*)(smem + P1_BHI);
    const __nv_bfloat16* Blo = (const __nv_bfloat16*)(smem + P1_BLO);
    const __nv_bfloat16* Xhi = (const __nv_bfloat16*)(smem + P1_XHI);
    const __nv_bfloat16* Xlo = (const __nv_bfloat16*)(smem + P1_XLO);

    const int tid  = threadIdx.x;
    const int ch   = blockIdx.x;
    const int pair = blockIdx.y;
    const int b    = pair / NHD;
    const int hh   = pair % NHD;
    const size_t rowbase = ((size_t)b * LEN + ch * TC) * NHD + hh;

    // ---- x raw staging via cp.async (fires first, no dependencies) ----
    {
        unsigned xb = smem_u32(xraw);
        #pragma unroll
        for (int j = 0; j < 4; ++j) {
            int i = tid + j * THREADS;          // float4 idx; t = i>>4, c = i&15
            int t = i >> 4, c = i & 15;
            cpa16(xb + i * 16, x + (rowbase + (size_t)t*NHD) * DH + c * 4);
        }
        asm volatile("cp.async.commit_group;\n" ::: "memory");
    }

    // ---- decay logs (A loads overlap with x cp.async) ----
    if (tid < TC) lcp[tid] = neg_sp_abs(A[rowbase + (size_t)tid * NHD], dp[hh]);

    // ---- stage B [t][s] bf16 hi/lo (independent of the scan) ----
    for (int i = tid; i < TC * 32; i += THREADS) {
        int t = i >> 5, c4 = i & 31;
        float4 v = ((const float4*)(Bm + (rowbase + (size_t)t*NHD) * DS))[c4];
        uint2 hi, lo;  split4(v, hi, lo);
        int off = t * (LDC*2) + c4 * 8;
        *(uint2*)(smem + P1_BHI + off) = hi;
        *(uint2*)(smem + P1_BLO + off) = lo;
    }
    __syncthreads();
    scan64(lcp, tid);
    if (tid < TC) lw[tid] = __expf(lcp[TC-1] - lcp[tid]);
    if (tid == 0) g_P[pair*NCH + ch] = __expf(lcp[TC-1]);
    asm volatile("cp.async.wait_group 0;\n" ::: "memory");
    __syncthreads();

    // ---- split + scale x from smem raw ----
    #pragma unroll
    for (int j = 0; j < 4; ++j) {
        int i = tid + j * THREADS;
        int t = i >> 4, c = i & 15;
        float4 v = ((const float4*)xraw)[i];
        float wt = lw[t];
        v.x *= wt; v.y *= wt; v.z *= wt; v.w *= wt;
        uint2 hi, lo;  split4(v, hi, lo);
        int off = t * (LDX*2) + c * 8;
        *(uint2*)(smem + P1_XHI + off) = hi;
        *(uint2*)(smem + P1_XLO + off) = lo;
    }
    __syncthreads();

    // WMMA: warp w owns m-tile (s) = w, n-tiles (d) 0..3
    const int w = tid >> 5;
    wmma::fragment<wmma::accumulator, 16, 16, 16, float> acc[4];
    #pragma unroll
    for (int nt = 0; nt < 4; ++nt) wmma::fill_fragment(acc[nt], 0.f);
    wmma::fragment<wmma::matrix_a, 16, 16, 16, __nv_bfloat16, wmma::col_major> ahi, alo;
    wmma::fragment<wmma::matrix_b, 16, 16, 16, __nv_bfloat16, wmma::row_major> bhi, blo;

    #pragma unroll
    for (int ks = 0; ks < 4; ++ks) {
        wmma::load_matrix_sync(ahi, Bhi + ks*16*LDC + w*16, LDC);
        wmma::load_matrix_sync(alo, Blo + ks*16*LDC + w*16, LDC);
        #pragma unroll
        for (int nt = 0; nt < 4; ++nt) {
            wmma::load_matrix_sync(bhi, Xhi + ks*16*LDX + nt*16, LDX);
            wmma::load_matrix_sync(blo, Xlo + ks*16*LDX + nt*16, LDX);
            wmma::mma_sync(acc[nt], ahi, bhi, acc[nt]);
            wmma::mma_sync(acc[nt], ahi, blo, acc[nt]);
            wmma::mma_sync(acc[nt], alo, bhi, acc[nt]);
        }
    }
    float* Sdst = g_S + ((size_t)(pair*NCH + ch)) * DH * DS;   // [s][d]
    #pragma unroll
    for (int nt = 0; nt < 4; ++nt)
        wmma::store_matrix_sync(Sdst + w*16*DH + nt*16, acc[nt],
                                DH, wmma::mem_row_major);
}

// =================================================================
// Pass 2: exclusive chunk scan (R15 measured config: grid NPAIRx8,
// one chain per thread, static prefetch depth 2)
// =================================================================
__global__ __launch_bounds__(THREADS, 8)
void pass2_kernel() {
    const int pair = blockIdx.x;
    const int idx  = blockIdx.y * THREADS + threadIdx.x;
    const float* Pp = g_P + pair * NCH;
    const size_t base = (size_t)pair * NCH * 2048 + idx;

    float4 Hr   = make_float4(0.f, 0.f, 0.f, 0.f);
    float4 nxt0 = ((const float4*)g_S)[base];
    float4 nxt1 = ((const float4*)g_S)[base + 2048];
    #pragma unroll 4
    for (int ch = 0; ch < NCH; ++ch) {
        float4 cur = nxt0;
        nxt0 = nxt1;
        if (ch + 2 < NCH) nxt1 = ((const float4*)g_S)[base + (size_t)(ch+2)*2048];
        uint2 hi, lo;  split4(Hr, hi, lo);
        ((uint2*)g_Hhi)[base + (size_t)ch*2048] = hi;
        ((uint2*)g_Hlo)[base + (size_t)ch*2048] = lo;
        const float P = Pp[ch];
        Hr.x = P*Hr.x + cur.x;  Hr.y = P*Hr.y + cur.y;
        Hr.z = P*Hr.z + cur.z;  Hr.w = P*Hr.w + cur.w;
    }
}

// =================================================================
// Pass 3 (WMMA, k-split staging -> 3 CTAs/SM): unchanged from R15.
// =================================================================
#define P3_LCP  0
#define P3_GINV 256
#define P3_ELC  512
#define P3_STG  1024
#define P3_CHI  (P3_STG)
#define P3_CLO  (P3_CHI + TC*LDK*2)
#define P3_BHI  (P3_CLO + TC*LDK*2)
#define P3_BLO  (P3_BHI + TC*LDK*2)
#define P3_HHI  (P3_BLO + TC*LDK*2)
#define P3_HLO  (P3_HHI + TC*LDH*2)
#define P3_STGE (P3_HLO + TC*LDH*2)        // 56320
#define P3_X    (P3_STGE)                  // fp32 64x64 (dedicated)
#define SMEM3   (P3_X + TC*DH*4)           // 72704 -> 3 CTAs/SM
#define P3_W    (P3_STG)                   // fp32 64 x LDW (alias)
#define P3_Y    (P3_W + TC*LDW*4)

__global__ __launch_bounds__(THREADS, 3)
void pass3_kernel(const float* __restrict__ x,
                  const float* __restrict__ Bm,
                  const float* __restrict__ Cm,
                  const float* __restrict__ A,
                  const float* __restrict__ dp,
                  float* __restrict__ out) {
    extern __shared__ __align__(128) char smem[];
    float* lcp  = (float*)(smem + P3_LCP);
    float* ginv = (float*)(smem + P3_GINV);
    float* elc  = (float*)(smem + P3_ELC);
    float* Wsh  = (float*)(smem + P3_W);
    float* Ysh  = (float*)(smem + P3_Y);
    float* xs   = (float*)(smem + P3_X);

    const int tid  = threadIdx.x;
    const int ch   = blockIdx.x;
    const int pair = blockIdx.y;
    const int b    = pair / NHD;
    const int hh   = pair % NHD;
    const size_t rowbase = ((size_t)b * LEN + ch * TC) * NHD + hh;

    // ---- stage x via cp.async into dedicated buffer ----
    {
        unsigned xb = smem_u32(xs);
        #pragma unroll
        for (int j = 0; j < 4; ++j) {
            int i = tid + j * THREADS;
            int t = i >> 4, c = i & 15;
            cpa16(xb + i * 16, x + (rowbase + (size_t)t*NHD) * DH + c * 4);
        }
        asm volatile("cp.async.commit_group;\n" ::: "memory");
    }

    if (tid < TC) {
        float la = neg_sp_abs(A[rowbase + (size_t)tid * NHD], dp[hh]);
        lcp[tid]  = la;
        ginv[tid] = fminf(__expf(-la), 1e30f);
    }
    __syncthreads();
    scan64(lcp, tid);
    if (tid < TC) elc[tid] = __expf(lcp[tid]);

    // ---- GEMM1 over two k-halves ----
    const int w = tid >> 5;
    wmma::fragment<wmma::accumulator, 16, 16, 16, float> acc[4];
    #pragma unroll
    for (int nt = 0; nt < 4; ++nt) wmma::fill_fragment(acc[nt], 0.f);

    const __nv_bfloat16* Hh_g = g_Hhi + (size_t)(pair*NCH + ch) * (DH*DS);
    const __nv_bfloat16* Hl_g = g_Hlo + (size_t)(pair*NCH + ch) * (DH*DS);

    #pragma unroll
    for (int kh = 0; kh < 2; ++kh) {
        {
            unsigned hb = smem_u32(smem + P3_HHI);
            unsigned lb = smem_u32(smem + P3_HLO);
            const uint4* Hh16 = (const uint4*)(Hh_g + kh * 64 * DH);
            const uint4* Hl16 = (const uint4*)(Hl_g + kh * 64 * DH);
            #pragma unroll
            for (int j = 0; j < 2; ++j) {
                int i = tid + j * THREADS;      // [0,512): s = i>>3, c = i&7
                int s = i >> 3, c = i & 7;
                unsigned off = s * (LDH*2) + c * 16;
                cpa16(hb + off, Hh16 + i);
                cpa16(lb + off, Hl16 + i);
            }
            asm volatile("cp.async.commit_group;\n" ::: "memory");
        }
        for (int i = tid; i < TC * 16; i += THREADS) {
            int t = i >> 4, c4 = i & 15;
            const size_t gofs = (rowbase + (size_t)t*NHD) * DS + kh * 64;
            float4 vc = ((const float4*)(Cm + gofs))[c4];
            float4 vb = ((const float4*)(Bm + gofs))[c4];
            uint2 hi, lo;
            int off = t * (LDK*2) + c4 * 8;
            split4(vc, hi, lo);
            *(uint2*)(smem + P3_CHI + off) = hi;
            *(uint2*)(smem + P3_CLO + off) = lo;
            split4(vb, hi, lo);
            *(uint2*)(smem + P3_BHI + off) = hi;
            *(uint2*)(smem + P3_BLO + off) = lo;
        }
        asm volatile("cp.async.wait_group 0;\n" ::: "memory");
        __syncthreads();

        {
            wmma::fragment<wmma::matrix_a, 16, 16, 16, __nv_bfloat16, wmma::row_major> ahi, alo;
            const __nv_bfloat16* Cb = (const __nv_bfloat16*)(smem + P3_CHI);
            const __nv_bfloat16* Cl = (const __nv_bfloat16*)(smem + P3_CLO);
            if (w < 4) {   // W = C . B^T  (causal skip)
                const __nv_bfloat16* Db = (const __nv_bfloat16*)(smem + P3_BHI);
                const __nv_bfloat16* Dl = (const __nv_bfloat16*)(smem + P3_BLO);
                wmma::fragment<wmma::matrix_b, 16, 16, 16, __nv_bfloat16, wmma::col_major> bhi, blo;
                #pragma unroll
                for (int ks = 0; ks < 4; ++ks) {
                    wmma::load_matrix_sync(ahi, Cb + w*16*LDK + ks*16, LDK);
                    wmma::load_matrix_sync(alo, Cl + w*16*LDK + ks*16, LDK);
                    #pragma unroll
                    for (int nt = 0; nt < 4; ++nt) {
                        if (nt > w) break;
                        wmma::load_matrix_sync(bhi, Db + nt*16*LDK + ks*16, LDK);
                        wmma::load_matrix_sync(blo, Dl + nt*16*LDK + ks*16, LDK);
                        wmma::mma_sync(acc[nt], ahi, bhi, acc[nt]);
                        wmma::mma_sync(acc[nt], ahi, blo, acc[nt]);
                        wmma::mma_sync(acc[nt], alo, bhi, acc[nt]);
                    }
                }
            } else {       // Y1 = C . H'
                const int mt = w - 4;
                const __nv_bfloat16* Hb = (const __nv_bfloat16*)(smem + P3_HHI);
                const __nv_bfloat16* Hl = (const __nv_bfloat16*)(smem + P3_HLO);
                wmma::fragment<wmma::matrix_b, 16, 16, 16, __nv_bfloat16, wmma::row_major> bhi, blo;
                #pragma unroll
                for (int ks = 0; ks < 4; ++ks) {
                    wmma::load_matrix_sync(ahi, Cb + mt*16*LDK + ks*16, LDK);
                    wmma::load_matrix_sync(alo, Cl + mt*16*LDK + ks*16, LDK);
                    #pragma unroll
                    for (int nt = 0; nt < 4; ++nt) {
                        wmma::load_matrix_sync(bhi, Hb + ks*16*LDH + nt*16, LDH);
                        wmma::load_matrix_sync(blo, Hl + ks*16*LDH + nt*16, LDH);
                        wmma::mma_sync(acc[nt], ahi, bhi, acc[nt]);
                        wmma::mma_sync(acc[nt], ahi, blo, acc[nt]);
                        wmma::mma_sync(acc[nt], alo, bhi, acc[nt]);
                    }
                }
            }
        }
        __syncthreads();
    }

    // ---- store W / Y into alias region ----
    if (w < 4) {
        #pragma unroll
        for (int nt = 0; nt < 4; ++nt) {
            if (nt > w) break;
            wmma::store_matrix_sync(Wsh + w*16*LDW + nt*16, acc[nt],
                                    LDW, wmma::mem_row_major);
        }
    } else {
        #pragma unroll
        for (int nt = 0; nt < 4; ++nt)
            wmma::store_matrix_sync(Ysh + (w-4)*16*LDW + nt*16, acc[nt],
                                    LDW, wmma::mem_row_major);
    }
    __syncthreads();

    // ---- epilogue: decay/mask W, scale Y1 ----
    {
        const int t  = tid >> 2;
        const int s0 = (tid & 3) * 16;
        float f = (s0 <= t) ? __expf(lcp[t] - lcp[s0]) : 0.f;
        float* wr = Wsh + t * LDW + s0;
        float* yr = Ysh + t * LDW + s0;
        const float et = elc[t];
        #pragma unroll
        for (int i2 = 0; i2 < 16; ++i2) {
            int s = s0 + i2;
            if (i2) f *= ginv[s];
            wr[i2] = (s <= t) ? f * wr[i2] : 0.f;
            yr[i2] = et * yr[i2];
        }
    }
    __syncthreads();

    // ---- GEMM2: Y = Y1 + W . x  (causal, fp32), warp-balanced ----
    {
        const int lane = tid & 31;
        const int wq   = tid >> 5;
        #pragma unroll
        for (int half = 0; half < 2; ++half) {
            const int r = half ? (15 - wq) : wq;
            float ya0[4], ya1[4];
            #pragma unroll
            for (int i = 0; i < 4; ++i) {
                float2 yv = *(const float2*)(Ysh + (4*r + i) * LDW + 2*lane);
                ya0[i] = yv.x;  ya1[i] = yv.y;
            }
            for (int s4 = 0; s4 <= r; ++s4) {
                float4 Wf[4];
                float2 xf[4];
                #pragma unroll
                for (int i = 0; i < 4; ++i)
                    Wf[i] = *(const float4*)(Wsh + (4*r + i) * LDW + 4*s4);
                #pragma unroll
                for (int k = 0; k < 4; ++k)
                    xf[k] = *(const float2*)(xs + (4*s4 + k) * DH + 2*lane);
                #pragma unroll
                for (int i = 0; i < 4; ++i) {
                    ya0[i] += Wf[i].x*xf[0].x + Wf[i].y*xf[1].x
                            + Wf[i].z*xf[2].x + Wf[i].w*xf[3].x;
                    ya1[i] += Wf[i].x*xf[0].y + Wf[i].y*xf[1].y
                            + Wf[i].z*xf[2].y + Wf[i].w*xf[3].y;
                }
            }
            #pragma unroll
            for (int i = 0; i < 4; ++i) {
                float* yout = out + (rowbase + (size_t)(4*r + i) * NHD) * DH + 2*lane;
                *(float2*)yout = make_float2(ya0[i], ya1[i]);
            }
        }
    }
}

// ------------- launch -------------
extern "C" void kernel_launch(void* const* d_in, const int* in_sizes, int n_in,
                              void* d_out, int out_size) {
    const float* x  = (const float*)d_in[0];
    const float* A  = (const float*)d_in[1];
    const float* Bm = (const float*)d_in[2];
    const float* Cm = (const float*)d_in[3];
    const float* dp = (const float*)d_in[4];
    (void)in_sizes; (void)n_in; (void)out_size;

    cudaFuncSetAttribute(pass1_kernel, cudaFuncAttributeMaxDynamicSharedMemorySize, SMEM1);
    cudaFuncSetAttribute(pass3_kernel, cudaFuncAttributeMaxDynamicSharedMemorySize, SMEM3);

    dim3 grid(NCH, NPAIR);
    pass1_kernel<<<grid, THREADS, SMEM1>>>(x, Bm, A, dp);
    pass2_kernel<<<dim3(NPAIR, 8), THREADS>>>();
    pass3_kernel<<<grid, THREADS, SMEM3>>>(x, Bm, Cm, A, dp, (float*)d_out);
}